// round 1
// baseline (speedup 1.0000x reference)
#include <cuda_runtime.h>
#include <cstdint>

#define NNODES 100000
#define NEDGES 1600000
#define FDIM   64
#define NF4    (NNODES * FDIM / 4)   // 1,600,000 float4

// Scratch (device globals: no allocation allowed).
__device__ float4 g_feat4[NF4];
__device__ float4 g_agg4[NF4];
__device__ float  g_deg[NNODES];
__device__ float  g_dis[NNODES];
__device__ int    g_idx64;  // 1 if edge_index is int64, 0 if int32

// ---------------------------------------------------------------------------
// Detect index width: int64 nonneg values => every odd 32-bit word is zero.
// P(false positive with int32 data) ~ (1e-5)^2048 == 0.
__global__ void detect_idx_kernel(const int* __restrict__ ei32) {
    int lane = threadIdx.x;
    int nz = 0;
    for (int i = lane; i < 2048; i += 32) nz |= ei32[2 * i + 1];
    unsigned m = __ballot_sync(0xffffffffu, nz != 0);
    if (lane == 0) g_idx64 = (m == 0) ? 1 : 0;
}

// ---------------------------------------------------------------------------
// init: feat = x, out = theta0 * x, agg = 0, deg = 0
__global__ void init_kernel(const float4* __restrict__ x4,
                            float4* __restrict__ out4, float th0) {
    int i = blockIdx.x * blockDim.x + threadIdx.x;
    if (i >= NF4) return;
    float4 v = x4[i];
    g_feat4[i] = v;
    float4 o; o.x = th0 * v.x; o.y = th0 * v.y; o.z = th0 * v.z; o.w = th0 * v.w;
    out4[i] = o;
    g_agg4[i] = make_float4(0.f, 0.f, 0.f, 0.f);
    if (i < NNODES) g_deg[i] = 0.f;
}

// ---------------------------------------------------------------------------
__global__ void deg_kernel(const void* __restrict__ eiv) {
    int e = blockIdx.x * blockDim.x + threadIdx.x;
    if (e >= NEDGES) return;
    int dst;
    if (g_idx64) dst = (int)((const long long*)eiv)[NEDGES + e];
    else         dst = ((const int*)eiv)[NEDGES + e];
    atomicAdd(&g_deg[dst], 1.0f);
}

__global__ void dis_kernel() {
    int i = blockIdx.x * blockDim.x + threadIdx.x;
    if (i >= NNODES) return;
    g_dis[i] = rsqrtf(fmaxf(g_deg[i], 1.0f));
}

// ---------------------------------------------------------------------------
// scatter: for each edge, agg[dst] += dis[src] * feat[src]
// 16 lanes per edge; one float4 gather + one red.global.add.v4 per lane.
__global__ void scatter_kernel(const void* __restrict__ eiv) {
    int t = blockIdx.x * blockDim.x + threadIdx.x;
    int e    = t >> 4;
    int lane = t & 15;
    if (e >= NEDGES) return;

    int src, dst;
    if (g_idx64) {
        const long long* ei = (const long long*)eiv;
        src = (int)ei[e];
        dst = (int)ei[NEDGES + e];
    } else {
        const int* ei = (const int*)eiv;
        src = ei[e];
        dst = ei[NEDGES + e];
    }

    float w = g_dis[src];
    float4 v = g_feat4[src * 16 + lane];

    float4* p = &g_agg4[dst * 16 + lane];
    unsigned long long gp;
    asm("cvta.to.global.u64 %0, %1;" : "=l"(gp) : "l"(p));
    asm volatile("red.global.add.v4.f32 [%0], {%1, %2, %3, %4};"
                 :: "l"(gp), "f"(w * v.x), "f"(w * v.y),
                    "f"(w * v.z), "f"(w * v.w)
                 : "memory");
}

// ---------------------------------------------------------------------------
// update: feat = feat - dis[n]*agg ; out += theta_k * feat ; agg = 0 (if more iters)
__global__ void update_kernel(float4* __restrict__ out4, float theta, int zero_agg) {
    int i = blockIdx.x * blockDim.x + threadIdx.x;
    if (i >= NF4) return;
    int node = i >> 4;           // 16 float4 per node row
    float dis = g_dis[node];

    float4 f = g_feat4[i];
    float4 a = g_agg4[i];
    float4 o = out4[i];

    float4 nf;
    nf.x = f.x - dis * a.x;
    nf.y = f.y - dis * a.y;
    nf.z = f.z - dis * a.z;
    nf.w = f.w - dis * a.w;
    g_feat4[i] = nf;

    o.x += theta * nf.x;
    o.y += theta * nf.y;
    o.z += theta * nf.z;
    o.w += theta * nf.w;
    out4[i] = o;

    if (zero_agg) g_agg4[i] = make_float4(0.f, 0.f, 0.f, 0.f);
}

// ---------------------------------------------------------------------------
extern "C" void kernel_launch(void* const* d_in, const int* in_sizes, int n_in,
                              void* d_out, int out_size) {
    const float4* x4 = (const float4*)d_in[0];
    const void*   ei = d_in[1];
    float4* out4 = (float4*)d_out;

    const float THETA[5] = {0.6f, -0.4f, 0.3f, -0.2f, 0.1f};

    detect_idx_kernel<<<1, 32>>>((const int*)ei);
    init_kernel<<<(NF4 + 255) / 256, 256>>>(x4, out4, THETA[0]);
    deg_kernel<<<(NEDGES + 255) / 256, 256>>>(ei);
    dis_kernel<<<(NNODES + 255) / 256, 256>>>();

    const int scatter_threads = NEDGES * 16;
    for (int k = 1; k <= 4; k++) {
        scatter_kernel<<<(scatter_threads + 255) / 256, 256>>>(ei);
        update_kernel<<<(NF4 + 255) / 256, 256>>>(out4, THETA[k], (k < 4) ? 1 : 0);
    }
}